// round 6
// baseline (speedup 1.0000x reference)
#include <cuda_runtime.h>
#include <math.h>

#define FRAME_SIZE 160
#define LPC_N 16
#define T_LEN 2400
#define T4 (T_LEN / 4)          // 600 float4 per row
#define N_FRAMES 15
#define B_SZ 1024

#define SPT 8                   // samples per thread
#define SLOTS (T_LEN / SPT)     // 300 threads of work per row
#define NTHREADS 320            // 10 warps; threads 300..319 idle

#define SCALE    (255.0f / 32768.0f)
#define SCALE_1  (32768.0f / 255.0f)

__device__ __forceinline__ float ex2_approx(float x) {
    float y; asm("ex2.approx.f32 %0, %1;" : "=f"(y) : "f"(x)); return y;
}
__device__ __forceinline__ float lg2_approx(float x) {
    float y; asm("lg2.approx.f32 %0, %1;" : "=f"(y) : "f"(x)); return y;
}

// mu-law (0..255) -> linear.  exp(u/128*ln256) == 2^(u/16)
__device__ __forceinline__ float u2l(float v) {
    float u = v - 128.0f;
    float m = fmaf(SCALE_1, ex2_approx(fabsf(u) * 0.0625f), -SCALE_1);
    return copysignf(m, u);
}
// l2u(-a) = clip(128 - copysign(16*log2(1 + SCALE*|a|), a), 0, 255)
__device__ __forceinline__ float l2u_neg(float a) {
    float u = lg2_approx(fmaf(SCALE, fabsf(a), 1.0f));
    float s = copysignf(16.0f, a);
    return fminf(fmaxf(fmaf(-s, u, 128.0f), 0.0f), 255.0f);
}

// One block per batch row. Thread s (0..299) produces samples [8s .. 8s+7]:
// loads its 24-sample window + 16 coefficients straight from global memory
// (no shared, no barriers), decodes in registers, 16-tap FIR, float4 stores.
__global__ __launch_bounds__(NTHREADS)
void diff_pred_kernel(const float4* __restrict__ sig,
                      const float*  __restrict__ lpc,
                      float4* __restrict__ out) {
    const int b = blockIdx.x;
    const int s = threadIdx.x;
    if (s >= SLOTS) return;

    const float4* srow = sig + (size_t)b * T4;

    // ---- issue all independent loads up front (MLP ~ 10) ----
    // window float4 groups: srow[2s - 4 + k], k = 0..5
    const int w0 = 2 * s - 4;
    float4 v[6];
    if (s >= 2) {
#pragma unroll
        for (int k = 0; k < 6; ++k) v[k] = srow[w0 + k];
    } else {
#pragma unroll
        for (int k = 0; k < 6; ++k)
            v[k] = (w0 + k >= 0) ? srow[w0 + k] : make_float4(128.f, 128.f, 128.f, 128.f);
        // 128 decodes to exactly 0 in the linear domain => correct zero-pad
    }
    // 16 per-frame coefficients (frame = 8s/160 = s/20)
    const int f = s / (FRAME_SIZE / SPT);
    const float4* lrow = (const float4*)(lpc + (size_t)b * (N_FRAMES * LPC_N) + f * LPC_N);
    float4 c0 = lrow[0], c1 = lrow[1], c2 = lrow[2], c3 = lrow[3];

    // ---- decode window to linear ----
    float x[24];
#pragma unroll
    for (int k = 0; k < 6; ++k) {
        x[4 * k]     = u2l(v[k].x);
        x[4 * k + 1] = u2l(v[k].y);
        x[4 * k + 2] = u2l(v[k].z);
        x[4 * k + 3] = u2l(v[k].w);
    }

    float c[LPC_N] = { c0.x, c0.y, c0.z, c0.w, c1.x, c1.y, c1.z, c1.w,
                       c2.x, c2.y, c2.z, c2.w, c3.x, c3.y, c3.z, c3.w };

    // ---- 16-tap FIR: a[j] = sum_i c[i] * x[16 + j - i] ----
    float a[SPT];
#pragma unroll
    for (int j = 0; j < SPT; ++j) a[j] = 0.0f;
#pragma unroll
    for (int i = 0; i < LPC_N; ++i) {
#pragma unroll
        for (int j = 0; j < SPT; ++j)
            a[j] = fmaf(c[i], x[16 + j - i], a[j]);
    }

    // ---- encode and store ----
    float4 r0, r1;
    r0.x = l2u_neg(a[0]); r0.y = l2u_neg(a[1]); r0.z = l2u_neg(a[2]); r0.w = l2u_neg(a[3]);
    r1.x = l2u_neg(a[4]); r1.y = l2u_neg(a[5]); r1.z = l2u_neg(a[6]); r1.w = l2u_neg(a[7]);

    float4* orow = out + (size_t)b * T4;
    orow[2 * s]     = r0;
    orow[2 * s + 1] = r1;
}

extern "C" void kernel_launch(void* const* d_in, const int* in_sizes, int n_in,
                              void* d_out, int out_size) {
    const float4* sig = (const float4*)d_in[0];  // (B, 2400, 1) f32
    const float*  lpc = (const float*)d_in[1];   // (B, 15, 16) f32
    float4* out = (float4*)d_out;                // (B, 2400, 1) f32

    diff_pred_kernel<<<B_SZ, NTHREADS>>>(sig, lpc, out);
}